// round 10
// baseline (speedup 1.0000x reference)
#include <cuda_runtime.h>
#include <cuda_fp16.h>
#include <cstdint>

#define KDIM   65536
#define MROWS  2048
#define NDFv   256
#define NCv    100
#define SPLITS 4
#define KPS    (KDIM / SPLITS)   // 16384
#define KC     64
#define NCHUNK (KPS / KC)        // 256
#define OFF_AH 0
#define OFF_AS 16384
#define OFF_BH 32768
#define OFF_BS 49152
#define STAGE  65536
#define SMEM_TOTAL (2 * STAGE)   // 128 KB

#define KAPPA_INV 32.0f
#define ONE_MK    0.96875f       // 1 - 2^-5

// device-global scratch (no cudaMalloc allowed)
__device__ __align__(16) unsigned short g_Bh[(size_t)NDFv * KDIM]; // [n][k] fp16 rn(w)
__device__ __align__(16) unsigned short g_Bs[(size_t)NDFv * KDIM]; // [n][k] fp16 Bh+32*Bl
__device__ float g_partial[(size_t)SPLITS * MROWS * NDFv];         // [split][row][col]

// ---------------- helpers (sm_80-class PTX only: valid on compute_103) ------
__device__ __forceinline__ uint32_t smem_u32(const void* p) {
    uint32_t a;
    asm("{ .reg .u64 t; cvta.to.shared.u64 t, %1; cvt.u32.u64 %0, t; }" : "=r"(a) : "l"(p));
    return a;
}
__device__ __forceinline__ uint32_t packh2(float lo, float hi) { // low half = rn16(lo)
    uint32_t r;
    asm("cvt.rn.f16x2.f32 %0, %1, %2;" : "=r"(r) : "f"(hi), "f"(lo));
    return r;
}
#define STS64V(a, r0, r1) \
    asm volatile("st.shared.v2.b32 [%0], {%1,%2};" :: "r"(a), "r"(r0), "r"(r1) : "memory")
#define CP_ASYNC16(dst, src) \
    asm volatile("cp.async.cg.shared.global [%0], [%1], 16;" :: "r"(dst), "l"(src) : "memory")
#define CP_COMMIT() asm volatile("cp.async.commit_group;" ::: "memory")
#define CP_WAIT0()  asm volatile("cp.async.wait_group 0;" ::: "memory")

__device__ __forceinline__ void ldsm4(uint32_t r[4], uint32_t a) {
    asm volatile("ldmatrix.sync.aligned.m8n8.x4.shared.b16 {%0,%1,%2,%3}, [%4];"
                 : "=r"(r[0]), "=r"(r[1]), "=r"(r[2]), "=r"(r[3]) : "r"(a));
}
__device__ __forceinline__ void mmaf16(float d[4], const uint32_t a[4],
                                       uint32_t b0, uint32_t b1) {
    asm volatile("mma.sync.aligned.m16n8k16.row.col.f32.f16.f16.f32 "
                 "{%0,%1,%2,%3},{%4,%5,%6,%7},{%8,%9},{%0,%1,%2,%3};"
                 : "+f"(d[0]), "+f"(d[1]), "+f"(d[2]), "+f"(d[3])
                 : "r"(a[0]), "r"(a[1]), "r"(a[2]), "r"(a[3]), "r"(b0), "r"(b1));
}

// ---------------- prepass: W [K,256] fp32 -> g_Bh/g_Bs [256][K] fp16 --------
__global__ __launch_bounds__(256) void bprep_kernel(const float* __restrict__ W) {
    __shared__ float tile[32][33];
    const int k0 = blockIdx.x * 32, n0 = blockIdx.y * 32;
    const int tx = threadIdx.x & 31, ty = threadIdx.x >> 5;
    #pragma unroll
    for (int i = 0; i < 4; i++)
        tile[ty * 4 + i][tx] = W[(size_t)(k0 + ty * 4 + i) * NDFv + n0 + tx];
    __syncthreads();
    #pragma unroll
    for (int i = 0; i < 4; i++) {
        const int n = ty * 4 + i;
        const float w = tile[tx][n];
        const __half bh = __float2half_rn(w);
        const float bhf = __half2float(bh);
        const float bl = w - bhf;
        const __half bs = __float2half_rn(fmaf(KAPPA_INV, bl, bhf));
        const size_t idx = (size_t)(n0 + n) * KDIM + k0 + tx;
        g_Bh[idx] = *(const unsigned short*)&bh;
        g_Bs[idx] = *(const unsigned short*)&bs;
    }
}

// ---------------- GEMM: fp16 2-pass kappa split, STS hidden in MMA stream ---
__global__ __launch_bounds__(256, 1) void gemm_mma_kernel(const float* __restrict__ A) {
    extern __shared__ char smem_dyn[];
    const uint32_t sbase = smem_u32(smem_dyn);
    const int tid = threadIdx.x;
    const int wid = tid >> 5, lane = tid & 31;
    const int mtile = blockIdx.x & 15;
    const int ntile = (blockIdx.x >> 4) & 1;
    const int split = blockIdx.x >> 5;
    const int wm = wid & 1, wn = wid >> 1;   // warp tile: m64 x n32

    // A loader: 2 threads per row (128 rows), each 32 k = 8 float4
    const int arow = tid >> 1, ahalf = tid & 1;
    const uint32_t xa = (uint32_t)((arow & 7) << 4);
    const float* Ag = A + (size_t)(mtile * 128 + arow) * KDIM + (size_t)split * KPS + ahalf * 32;
    const unsigned short* Bhg = g_Bh + (size_t)(ntile * 128 + arow) * KDIM
                                + (size_t)split * KPS + ahalf * 32;
    const unsigned short* Bsg = g_Bs + (size_t)(ntile * 128 + arow) * KDIM
                                + (size_t)split * KPS + ahalf * 32;

    // ldmatrix lane mapping
    const int a_r = (lane & 7) + ((lane >> 3) & 1) * 8;
    const uint32_t a_c16 = (uint32_t)(((lane >> 4) & 1) * 16);
    const uint32_t xf = (uint32_t)((a_r & 7) << 4);
    uint32_t colx[4];
    #pragma unroll
    for (int ks = 0; ks < 4; ks++) colx[ks] = (((uint32_t)ks << 5) | a_c16) ^ xf;

    float acc1[4][4][4] = {};   // P1 = Ah*Bh
    float acc2[4][4][4] = {};   // P2 = As*Bs
    float4 a_ld[8];

    // convert + STS of a_ld into stage `dst`
#define STS_A(dst) do {                                                          \
    _Pragma("unroll")                                                            \
    for (int i = 0; i < 8; i++) {                                                \
        const float4 f = a_ld[i];                                                \
        const uint32_t h0 = packh2(f.x, f.y);                                    \
        const uint32_t h1 = packh2(f.z, f.w);                                    \
        const float ahx = __half2float(*(const __half*)&h0);                     \
        const float ahy = __half2float(((const __half*)&h0)[1]);                 \
        const float ahz = __half2float(*(const __half*)&h1);                     \
        const float ahw = __half2float(((const __half*)&h1)[1]);                 \
        const uint32_t s0 = packh2(fmaf(-ONE_MK, ahx, f.x), fmaf(-ONE_MK, ahy, f.y)); \
        const uint32_t s1 = packh2(fmaf(-ONE_MK, ahz, f.z), fmaf(-ONE_MK, ahw, f.w)); \
        const uint32_t off = (uint32_t)(arow * 128) +                            \
                             (((uint32_t)(ahalf * 64 + i * 8)) ^ xa);            \
        STS64V((dst) + OFF_AH + off, h0, h1);                                    \
        STS64V((dst) + OFF_AS + off, s0, s1);                                    \
    } } while (0)

#define LDG_A(c) do {                                                            \
    const float* _p = Ag + (size_t)(c) * KC;                                     \
    _Pragma("unroll")                                                            \
    for (int i = 0; i < 8; i++) a_ld[i] = *(const float4*)(_p + i * 4);          \
    } while (0)

#define CPA_B(c, dst) do {                                                       \
    const unsigned short* _bh = Bhg + (size_t)(c) * KC;                          \
    const unsigned short* _bs = Bsg + (size_t)(c) * KC;                          \
    _Pragma("unroll")                                                            \
    for (int j = 0; j < 4; j++) {                                                \
        const uint32_t off = (uint32_t)(arow * 128) +                            \
                             ((((uint32_t)(ahalf * 4 + j)) << 4) ^ xa);          \
        CP_ASYNC16((dst) + OFF_BH + off, _bh + j * 8);                           \
        CP_ASYNC16((dst) + OFF_BS + off, _bs + j * 8);                           \
    }                                                                            \
    CP_COMMIT(); } while (0)

#define KSTEP(ks) do {                                                           \
    uint32_t ah[4][4], bh[2][4];                                                 \
    _Pragma("unroll")                                                            \
    for (int mf = 0; mf < 4; mf++)                                               \
        ldsm4(ah[mf], st + OFF_AH + (uint32_t)((wm * 64 + mf * 16 + a_r) * 128) + colx[ks]); \
    _Pragma("unroll")                                                            \
    for (int g = 0; g < 2; g++)                                                  \
        ldsm4(bh[g], st + OFF_BH + (uint32_t)((wn * 32 + g * 16 + a_r) * 128) + colx[ks]);   \
    _Pragma("unroll")                                                            \
    for (int mf = 0; mf < 4; mf++)                                               \
        _Pragma("unroll")                                                        \
        for (int g = 0; g < 2; g++) {                                            \
            mmaf16(acc1[mf][g * 2 + 0], ah[mf], bh[g][0], bh[g][2]);             \
            mmaf16(acc1[mf][g * 2 + 1], ah[mf], bh[g][1], bh[g][3]);             \
        }                                                                        \
    uint32_t as[4][4], bs[2][4];                                                 \
    _Pragma("unroll")                                                            \
    for (int mf = 0; mf < 4; mf++)                                               \
        ldsm4(as[mf], st + OFF_AS + (uint32_t)((wm * 64 + mf * 16 + a_r) * 128) + colx[ks]); \
    _Pragma("unroll")                                                            \
    for (int g = 0; g < 2; g++)                                                  \
        ldsm4(bs[g], st + OFF_BS + (uint32_t)((wn * 32 + g * 16 + a_r) * 128) + colx[ks]);   \
    _Pragma("unroll")                                                            \
    for (int mf = 0; mf < 4; mf++)                                               \
        _Pragma("unroll")                                                        \
        for (int g = 0; g < 2; g++) {                                            \
            mmaf16(acc2[mf][g * 2 + 0], as[mf], bs[g][0], bs[g][2]);             \
            mmaf16(acc2[mf][g * 2 + 1], as[mf], bs[g][1], bs[g][3]);             \
        } } while (0)

    // ---- prologue: stage 0 fully populated, stage 1 in flight ----
    LDG_A(0);
    CPA_B(0, sbase);                 // group: B0
    STS_A(sbase);                    // A0 -> stage 0
    CP_WAIT0();                      // B0 arrived
    __syncthreads();                 // stage 0 published
    LDG_A(1);                        // A regs for chunk 1
    CPA_B(1, sbase + STAGE);         // group: B1 -> stage 1

    for (int it = 0; it < NCHUNK; it++) {
        const uint32_t st  = sbase + (uint32_t)((it & 1) * STAGE);
        const uint32_t st2 = sbase + (uint32_t)(((it + 1) & 1) * STAGE);

        KSTEP(0);
        KSTEP(1);
        if (it + 1 < NCHUNK) STS_A(st2);   // hide A convert+STS under MMAs
        KSTEP(2);
        KSTEP(3);
        if (it + 1 < NCHUNK) {
            CP_WAIT0();                    // B(it+1) arrived (issued a chunk ago)
            __syncthreads();               // publish stage it+1; stage it free
        }
        if (it + 2 < NCHUNK) {
            LDG_A(it + 2);                 // A regs for chunk it+2
            CPA_B(it + 2, st);             // B(it+2) -> freed stage
        }
    }

    // epilogue: partial = (1-kappa)*P1 + P2
    float* pbase = g_partial + (size_t)split * MROWS * NDFv;
    #pragma unroll
    for (int mf = 0; mf < 4; mf++)
        #pragma unroll
        for (int nf = 0; nf < 4; nf++) {
            const int row = mtile * 128 + wm * 64 + mf * 16 + (lane >> 2);
            const int col = ntile * 128 + wn * 32 + nf * 8 + (lane & 3) * 2;
            float* p = pbase + (size_t)row * NDFv + col;
            const float v0 = fmaf(ONE_MK, acc1[mf][nf][0], acc2[mf][nf][0]);
            const float v1 = fmaf(ONE_MK, acc1[mf][nf][1], acc2[mf][nf][1]);
            const float v2 = fmaf(ONE_MK, acc1[mf][nf][2], acc2[mf][nf][2]);
            const float v3 = fmaf(ONE_MK, acc1[mf][nf][3], acc2[mf][nf][3]);
            *(float2*)p = make_float2(v0, v1);
            *(float2*)(p + 8 * NDFv) = make_float2(v2, v3);
        }
}

// ---------------- split-K reduce: zall = (sum partials + bias) * mask -------
__global__ __launch_bounds__(256) void reduce_kernel(const float* __restrict__ bias,
                                                     const int* __restrict__ mask,
                                                     float* __restrict__ zall) {
    const int i = blockIdx.x * 256 + threadIdx.x;   // float2 units
    const int row = i >> 7;
    const int col = (i & 127) * 2;
    float2 s = make_float2(0.f, 0.f);
    #pragma unroll
    for (int sp = 0; sp < SPLITS; sp++) {
        const float2 v = *(const float2*)&g_partial[(size_t)sp * MROWS * NDFv +
                                                    (size_t)row * NDFv + col];
        s.x += v.x; s.y += v.y;
    }
    const float m = mask[row] ? 1.0f : 0.0f;
    s.x = (s.x + bias[col]) * m;
    s.y = (s.y + bias[col + 1]) * m;
    *(float2*)&zall[(size_t)row * NDFv + col] = s;
}

// ---------------- student-t + normalize + argmax (4 rows / block) -----------
__global__ __launch_bounds__(128) void cluster_kernel(const float* __restrict__ Z,
                                                      const float* __restrict__ cent,
                                                      const int* __restrict__ mask,
                                                      float* __restrict__ S,
                                                      float* __restrict__ Cidx) {
    const int tid = threadIdx.x;
    const int row0 = blockIdx.x * 4;
    __shared__ __align__(16) float zs[4][256];
    __shared__ float stmp[4][128];
    __shared__ float red_s[4];
    __shared__ int   red_i[4];

    #pragma unroll
    for (int i = 0; i < 8; i++) {
        const int idx = i * 128 + tid;
        zs[idx >> 8][idx & 255] = Z[(size_t)row0 * 256 + idx];
    }
    __syncthreads();

    float v[4] = {0.f, 0.f, 0.f, 0.f};
    if (tid < NCv) {
        const float4* c4 = (const float4*)(cent + (size_t)tid * NDFv);
        float d[4] = {0.f, 0.f, 0.f, 0.f};
        #pragma unroll 4
        for (int j = 0; j < NDFv / 4; j++) {
            const float4 cv = c4[j];
            #pragma unroll
            for (int r = 0; r < 4; r++) {
                const float4 zv = ((const float4*)zs[r])[j];
                const float dx = zv.x - cv.x, dy = zv.y - cv.y;
                const float dz = zv.z - cv.z, dw = zv.w - cv.w;
                d[r] += dx * dx + dy * dy + dz * dz + dw * dw;
            }
        }
        #pragma unroll
        for (int r = 0; r < 4; r++)
            v[r] = 1.0f / (1.0f + sqrtf(fmaxf(d[r], 0.0f)));
    }
    #pragma unroll
    for (int r = 0; r < 4; r++) stmp[r][tid] = v[r];
    __syncthreads();

    {   // warp r reduces row r
        const int r = tid >> 5, l = tid & 31;
        float sum = 0.0f, best = -1.0f;
        int bidx = 0;
        for (int k = l; k < NCv; k += 32) {
            const float x = stmp[r][k];
            sum += x;
            if (x > best) { best = x; bidx = k; }
        }
        #pragma unroll
        for (int off = 16; off > 0; off >>= 1) {
            sum += __shfl_down_sync(0xffffffffu, sum, off);
            const float ob = __shfl_down_sync(0xffffffffu, best, off);
            const int   oi = __shfl_down_sync(0xffffffffu, bidx, off);
            if (ob > best || (ob == best && oi < bidx)) { best = ob; bidx = oi; }
        }
        if (l == 0) { red_s[r] = sum; red_i[r] = bidx; }
    }
    __syncthreads();

    #pragma unroll
    for (int r = 0; r < 4; r++) {
        const int row = row0 + r;
        const bool m = mask[row] != 0;
        const float inv = m ? (1.0f / red_s[r]) : 0.0f;
        if (tid < NCv) S[(size_t)row * NCv + tid] = v[r] * inv;
        if (tid == 0)  Cidx[row] = m ? (float)red_i[r] : 0.0f;
    }
}

// ---------------------------------------------------------------------------
extern "C" void kernel_launch(void* const* d_in, const int* in_sizes, int n_in,
                              void* d_out, int out_size) {
    (void)in_sizes; (void)n_in; (void)out_size;
    const float* z_roi = (const float*)d_in[0];
    const int*   mask  = (const int*)d_in[1];
    const float* w_emb = (const float*)d_in[2];
    const float* b_emb = (const float*)d_in[3];
    const float* cent  = (const float*)d_in[4];

    float* out  = (float*)d_out;
    float* zall = out;
    float* S    = out + (size_t)MROWS * NDFv;
    float* Cx   = S + (size_t)MROWS * NCv;

    cudaFuncSetAttribute(gemm_mma_kernel, cudaFuncAttributeMaxDynamicSharedMemorySize, SMEM_TOTAL);

    bprep_kernel<<<dim3(KDIM / 32, NDFv / 32), 256>>>(w_emb);
    gemm_mma_kernel<<<128, 256, SMEM_TOTAL>>>(z_roi);
    reduce_kernel<<<(MROWS * NDFv / 2) / 256, 256>>>(b_emb, mask, zall);
    cluster_kernel<<<MROWS / 4, 128>>>(zall, cent, mask, S, Cx);
}

// round 11
// speedup vs baseline: 1.5856x; 1.5856x over previous
#include <cuda_runtime.h>
#include <cuda_fp16.h>
#include <cstdint>

#define KDIM   65536
#define MROWS  2048
#define NDFv   256
#define NCv    100
#define SPLITS 4
#define KPS    (KDIM / SPLITS)   // 16384
#define KC     64
#define NCHUNK (KPS / KC)        // 256
#define OFF_AH 0
#define OFF_AS 16384
#define OFF_BH 32768
#define OFF_BS 49152
#define STAGE  65536
#define SMEM_TOTAL (2 * STAGE)   // 128 KB

#define NTHREADS 320             // 256 consumers + 64 producers
#define KAPPA_INV 32.0f
#define ONE_MK    0.96875f       // 1 - 2^-5

// device-global scratch (no cudaMalloc allowed)
__device__ __align__(16) unsigned short g_Bh[(size_t)NDFv * KDIM]; // [n][k] fp16 rn(w)
__device__ __align__(16) unsigned short g_Bs[(size_t)NDFv * KDIM]; // [n][k] fp16 Bh+32*Bl
__device__ float g_partial[(size_t)SPLITS * MROWS * NDFv];         // [split][row][col]

// ---------------- helpers (sm_80-class PTX only: valid on compute_103) ------
__device__ __forceinline__ uint32_t smem_u32(const void* p) {
    uint32_t a;
    asm("{ .reg .u64 t; cvta.to.shared.u64 t, %1; cvt.u32.u64 %0, t; }" : "=r"(a) : "l"(p));
    return a;
}
__device__ __forceinline__ uint32_t packh2(float lo, float hi) { // low half = rn16(lo)
    uint32_t r;
    asm("cvt.rn.f16x2.f32 %0, %1, %2;" : "=r"(r) : "f"(hi), "f"(lo));
    return r;
}
#define STS64V(a, r0, r1) \
    asm volatile("st.shared.v2.b32 [%0], {%1,%2};" :: "r"(a), "r"(r0), "r"(r1) : "memory")
#define CP_ASYNC16(dst, src) \
    asm volatile("cp.async.cg.shared.global [%0], [%1], 16;" :: "r"(dst), "l"(src) : "memory")
#define CP_COMMIT() asm volatile("cp.async.commit_group;" ::: "memory")
#define CP_WAIT0()  asm volatile("cp.async.wait_group 0;" ::: "memory")
#define MEMBAR_CTA() asm volatile("membar.cta;" ::: "memory")
#define BAR_SYNC(id)   asm volatile("bar.sync %0, %1;"   :: "r"(id), "r"(NTHREADS) : "memory")
#define BAR_ARRIVE(id) asm volatile("bar.arrive %0, %1;" :: "r"(id), "r"(NTHREADS) : "memory")
// barrier ids: 1+s = stage s FULL, 3+s = stage s EMPTY

__device__ __forceinline__ void ldsm4(uint32_t r[4], uint32_t a) {
    asm volatile("ldmatrix.sync.aligned.m8n8.x4.shared.b16 {%0,%1,%2,%3}, [%4];"
                 : "=r"(r[0]), "=r"(r[1]), "=r"(r[2]), "=r"(r[3]) : "r"(a));
}
__device__ __forceinline__ void mmaf16(float d[4], const uint32_t a[4],
                                       uint32_t b0, uint32_t b1) {
    asm volatile("mma.sync.aligned.m16n8k16.row.col.f32.f16.f16.f32 "
                 "{%0,%1,%2,%3},{%4,%5,%6,%7},{%8,%9},{%0,%1,%2,%3};"
                 : "+f"(d[0]), "+f"(d[1]), "+f"(d[2]), "+f"(d[3])
                 : "r"(a[0]), "r"(a[1]), "r"(a[2]), "r"(a[3]), "r"(b0), "r"(b1));
}

// ---------------- prepass: W [K,256] fp32 -> g_Bh/g_Bs [256][K] fp16 --------
__global__ __launch_bounds__(256) void bprep_kernel(const float* __restrict__ W) {
    __shared__ float tile[32][33];
    const int k0 = blockIdx.x * 32, n0 = blockIdx.y * 32;
    const int tx = threadIdx.x & 31, ty = threadIdx.x >> 5;
    #pragma unroll
    for (int i = 0; i < 4; i++)
        tile[ty * 4 + i][tx] = W[(size_t)(k0 + ty * 4 + i) * NDFv + n0 + tx];
    __syncthreads();
    #pragma unroll
    for (int i = 0; i < 4; i++) {
        const int n = ty * 4 + i;
        const float w = tile[tx][n];
        const __half bh = __float2half_rn(w);
        const float bhf = __half2float(bh);
        const float bl = w - bhf;
        const __half bs = __float2half_rn(fmaf(KAPPA_INV, bl, bhf));
        const size_t idx = (size_t)(n0 + n) * KDIM + k0 + tx;
        g_Bh[idx] = *(const unsigned short*)&bh;
        g_Bs[idx] = *(const unsigned short*)&bs;
    }
}

// ---------------- GEMM: fp16 2-pass kappa split, warp-specialized -----------
__global__ __launch_bounds__(NTHREADS, 1) void gemm_mma_kernel(const float* __restrict__ A) {
    extern __shared__ char smem_dyn[];
    const uint32_t sbase = smem_u32(smem_dyn);
    const int tid = threadIdx.x;
    const int mtile = blockIdx.x & 15;
    const int ntile = (blockIdx.x >> 4) & 1;
    const int split = blockIdx.x >> 5;

    if (tid >= 256) {
        // ================= PRODUCER (warps 8-9, 64 threads) =================
        const int pt = tid - 256;             // 0..63
        const int prow = pt >> 4;             // A: row offset within group of 4
        const int pkf4 = pt & 15;             // A: float4 index within row
        const int prow8 = pt >> 3;            // B: row offset within group of 8
        const int pseg = pt & 7;              // B: 16B segment within row

        const float* Abase0 = A + (size_t)(mtile * 128) * KDIM + (size_t)split * KPS
                              + pkf4 * 4;
        const unsigned short* Bh0 = g_Bh + (size_t)(ntile * 128) * KDIM
                                    + (size_t)split * KPS + pseg * 8;
        const unsigned short* Bs0 = g_Bs + (size_t)(ntile * 128) * KDIM
                                    + (size_t)split * KPS + pseg * 8;

        // A STS byte offsets per (b, j): row = b*32 + j*4 + prow
        // off = row*128 + ((pkf4*8) ^ ((row&7)<<4))
        float4 bufA[8], bufB[8];

#define PLDG(buf, it, b) do {                                                    \
    const float* _ab = Abase0 + (size_t)(it) * KC;                               \
    _Pragma("unroll")                                                            \
    for (int j = 0; j < 8; j++) {                                                \
        const int row = (b) * 32 + j * 4 + prow;                                 \
        (buf)[j] = *(const float4*)(_ab + (size_t)row * KDIM);                   \
    } } while (0)

#define PSTS(buf, st, b) do {                                                    \
    _Pragma("unroll")                                                            \
    for (int j = 0; j < 8; j++) {                                                \
        const int row = (b) * 32 + j * 4 + prow;                                 \
        const uint32_t off = (uint32_t)(row * 128) +                             \
                             (((uint32_t)(pkf4 * 8)) ^ ((uint32_t)((row & 7) << 4))); \
        const float4 f = (buf)[j];                                               \
        const uint32_t h0 = packh2(f.x, f.y);                                    \
        const uint32_t h1 = packh2(f.z, f.w);                                    \
        const float ahx = __half2float(*(const __half*)&h0);                     \
        const float ahy = __half2float(((const __half*)&h0)[1]);                 \
        const float ahz = __half2float(*(const __half*)&h1);                     \
        const float ahw = __half2float(((const __half*)&h1)[1]);                 \
        const uint32_t s0 = packh2(fmaf(-ONE_MK, ahx, f.x), fmaf(-ONE_MK, ahy, f.y)); \
        const uint32_t s1 = packh2(fmaf(-ONE_MK, ahz, f.z), fmaf(-ONE_MK, ahw, f.w)); \
        STS64V((st) + OFF_AH + off, h0, h1);                                     \
        STS64V((st) + OFF_AS + off, s0, s1);                                     \
    } } while (0)

        for (int it = 0; it < NCHUNK; it++) {
            const int s = it & 1;
            const uint32_t st = sbase + (uint32_t)(s * STAGE);
            if (it >= 2) BAR_SYNC(3 + s);        // wait stage empty

            // B -> cp.async (fills while we convert A)
            {
                const unsigned short* bh = Bh0 + (size_t)it * KC;
                const unsigned short* bs = Bs0 + (size_t)it * KC;
                #pragma unroll
                for (int j = 0; j < 16; j++) {
                    const int row = j * 8 + prow8;
                    const uint32_t off = (uint32_t)(row * 128) +
                        (((uint32_t)(pseg * 16)) ^ ((uint32_t)(prow8 << 4)));
                    CP_ASYNC16(st + OFF_BH + off, bh + (size_t)row * KDIM);
                    CP_ASYNC16(st + OFF_BS + off, bs + (size_t)row * KDIM);
                }
                CP_COMMIT();
            }
            // A: 4 batches, reg double-buffered
            PLDG(bufA, it, 0);
            PLDG(bufB, it, 1);
            PSTS(bufA, st, 0);
            PLDG(bufA, it, 2);
            PSTS(bufB, st, 1);
            PLDG(bufB, it, 3);
            PSTS(bufA, st, 2);
            PSTS(bufB, st, 3);
            CP_WAIT0();
            MEMBAR_CTA();
            BAR_ARRIVE(1 + s);                   // publish stage full
        }
        return;
    }

    // ================= CONSUMERS (warps 0-7, 256 threads) ===================
    const int wid = tid >> 5, lane = tid & 31;
    const int wm = wid & 1, wn = wid >> 1;       // warp tile: m64 x n32

    const int a_r = (lane & 7) + ((lane >> 3) & 1) * 8;
    const uint32_t a_c16 = (uint32_t)(((lane >> 4) & 1) * 16);
    const uint32_t xf = (uint32_t)((a_r & 7) << 4);
    uint32_t colx[4];
    #pragma unroll
    for (int ks = 0; ks < 4; ks++) colx[ks] = (((uint32_t)ks << 5) | a_c16) ^ xf;

    float acc1[4][4][4] = {};   // P1 = Ah*Bh
    float acc2[4][4][4] = {};   // P2 = As*Bs

#define KSTEP(ks) do {                                                           \
    uint32_t ah[4][4], bh[2][4];                                                 \
    _Pragma("unroll")                                                            \
    for (int mf = 0; mf < 4; mf++)                                               \
        ldsm4(ah[mf], st + OFF_AH + (uint32_t)((wm * 64 + mf * 16 + a_r) * 128) + colx[ks]); \
    _Pragma("unroll")                                                            \
    for (int g = 0; g < 2; g++)                                                  \
        ldsm4(bh[g], st + OFF_BH + (uint32_t)((wn * 32 + g * 16 + a_r) * 128) + colx[ks]);   \
    _Pragma("unroll")                                                            \
    for (int mf = 0; mf < 4; mf++)                                               \
        _Pragma("unroll")                                                        \
        for (int g = 0; g < 2; g++) {                                            \
            mmaf16(acc1[mf][g * 2 + 0], ah[mf], bh[g][0], bh[g][2]);             \
            mmaf16(acc1[mf][g * 2 + 1], ah[mf], bh[g][1], bh[g][3]);             \
        }                                                                        \
    uint32_t as[4][4], bs[2][4];                                                 \
    _Pragma("unroll")                                                            \
    for (int mf = 0; mf < 4; mf++)                                               \
        ldsm4(as[mf], st + OFF_AS + (uint32_t)((wm * 64 + mf * 16 + a_r) * 128) + colx[ks]); \
    _Pragma("unroll")                                                            \
    for (int g = 0; g < 2; g++)                                                  \
        ldsm4(bs[g], st + OFF_BS + (uint32_t)((wn * 32 + g * 16 + a_r) * 128) + colx[ks]);   \
    _Pragma("unroll")                                                            \
    for (int mf = 0; mf < 4; mf++)                                               \
        _Pragma("unroll")                                                        \
        for (int g = 0; g < 2; g++) {                                            \
            mmaf16(acc2[mf][g * 2 + 0], as[mf], bs[g][0], bs[g][2]);             \
            mmaf16(acc2[mf][g * 2 + 1], as[mf], bs[g][1], bs[g][3]);             \
        } } while (0)

    for (int it = 0; it < NCHUNK; it++) {
        const int s = it & 1;
        const uint32_t st = sbase + (uint32_t)(s * STAGE);
        BAR_SYNC(1 + s);                 // wait stage full
        KSTEP(0);
        KSTEP(1);
        KSTEP(2);
        KSTEP(3);
        if (it + 2 < NCHUNK) BAR_ARRIVE(3 + s);   // signal stage empty
    }

    // epilogue: partial = (1-kappa)*P1 + P2
    float* pbase = g_partial + (size_t)split * MROWS * NDFv;
    #pragma unroll
    for (int mf = 0; mf < 4; mf++)
        #pragma unroll
        for (int nf = 0; nf < 4; nf++) {
            const int row = mtile * 128 + wm * 64 + mf * 16 + (lane >> 2);
            const int col = ntile * 128 + wn * 32 + nf * 8 + (lane & 3) * 2;
            float* p = pbase + (size_t)row * NDFv + col;
            const float v0 = fmaf(ONE_MK, acc1[mf][nf][0], acc2[mf][nf][0]);
            const float v1 = fmaf(ONE_MK, acc1[mf][nf][1], acc2[mf][nf][1]);
            const float v2 = fmaf(ONE_MK, acc1[mf][nf][2], acc2[mf][nf][2]);
            const float v3 = fmaf(ONE_MK, acc1[mf][nf][3], acc2[mf][nf][3]);
            *(float2*)p = make_float2(v0, v1);
            *(float2*)(p + 8 * NDFv) = make_float2(v2, v3);
        }
}

// ---------------- split-K reduce: zall = (sum partials + bias) * mask -------
__global__ __launch_bounds__(256) void reduce_kernel(const float* __restrict__ bias,
                                                     const int* __restrict__ mask,
                                                     float* __restrict__ zall) {
    const int i = blockIdx.x * 256 + threadIdx.x;   // float2 units
    const int row = i >> 7;
    const int col = (i & 127) * 2;
    float2 s = make_float2(0.f, 0.f);
    #pragma unroll
    for (int sp = 0; sp < SPLITS; sp++) {
        const float2 v = *(const float2*)&g_partial[(size_t)sp * MROWS * NDFv +
                                                    (size_t)row * NDFv + col];
        s.x += v.x; s.y += v.y;
    }
    const float m = mask[row] ? 1.0f : 0.0f;
    s.x = (s.x + bias[col]) * m;
    s.y = (s.y + bias[col + 1]) * m;
    *(float2*)&zall[(size_t)row * NDFv + col] = s;
}

// ---------------- student-t + normalize + argmax (4 rows / block) -----------
__global__ __launch_bounds__(128) void cluster_kernel(const float* __restrict__ Z,
                                                      const float* __restrict__ cent,
                                                      const int* __restrict__ mask,
                                                      float* __restrict__ S,
                                                      float* __restrict__ Cidx) {
    const int tid = threadIdx.x;
    const int row0 = blockIdx.x * 4;
    __shared__ __align__(16) float zs[4][256];
    __shared__ float stmp[4][128];
    __shared__ float red_s[4];
    __shared__ int   red_i[4];

    #pragma unroll
    for (int i = 0; i < 8; i++) {
        const int idx = i * 128 + tid;
        zs[idx >> 8][idx & 255] = Z[(size_t)row0 * 256 + idx];
    }
    __syncthreads();

    float v[4] = {0.f, 0.f, 0.f, 0.f};
    if (tid < NCv) {
        const float4* c4 = (const float4*)(cent + (size_t)tid * NDFv);
        float d[4] = {0.f, 0.f, 0.f, 0.f};
        #pragma unroll 4
        for (int j = 0; j < NDFv / 4; j++) {
            const float4 cv = c4[j];
            #pragma unroll
            for (int r = 0; r < 4; r++) {
                const float4 zv = ((const float4*)zs[r])[j];
                const float dx = zv.x - cv.x, dy = zv.y - cv.y;
                const float dz = zv.z - cv.z, dw = zv.w - cv.w;
                d[r] += dx * dx + dy * dy + dz * dz + dw * dw;
            }
        }
        #pragma unroll
        for (int r = 0; r < 4; r++)
            v[r] = 1.0f / (1.0f + sqrtf(fmaxf(d[r], 0.0f)));
    }
    #pragma unroll
    for (int r = 0; r < 4; r++) stmp[r][tid] = v[r];
    __syncthreads();

    {   // warp r reduces row r
        const int r = tid >> 5, l = tid & 31;
        float sum = 0.0f, best = -1.0f;
        int bidx = 0;
        for (int k = l; k < NCv; k += 32) {
            const float x = stmp[r][k];
            sum += x;
            if (x > best) { best = x; bidx = k; }
        }
        #pragma unroll
        for (int off = 16; off > 0; off >>= 1) {
            sum += __shfl_down_sync(0xffffffffu, sum, off);
            const float ob = __shfl_down_sync(0xffffffffu, best, off);
            const int   oi = __shfl_down_sync(0xffffffffu, bidx, off);
            if (ob > best || (ob == best && oi < bidx)) { best = ob; bidx = oi; }
        }
        if (l == 0) { red_s[r] = sum; red_i[r] = bidx; }
    }
    __syncthreads();

    #pragma unroll
    for (int r = 0; r < 4; r++) {
        const int row = row0 + r;
        const bool m = mask[row] != 0;
        const float inv = m ? (1.0f / red_s[r]) : 0.0f;
        if (tid < NCv) S[(size_t)row * NCv + tid] = v[r] * inv;
        if (tid == 0)  Cidx[row] = m ? (float)red_i[r] : 0.0f;
    }
}

// ---------------------------------------------------------------------------
extern "C" void kernel_launch(void* const* d_in, const int* in_sizes, int n_in,
                              void* d_out, int out_size) {
    (void)in_sizes; (void)n_in; (void)out_size;
    const float* z_roi = (const float*)d_in[0];
    const int*   mask  = (const int*)d_in[1];
    const float* w_emb = (const float*)d_in[2];
    const float* b_emb = (const float*)d_in[3];
    const float* cent  = (const float*)d_in[4];

    float* out  = (float*)d_out;
    float* zall = out;
    float* S    = out + (size_t)MROWS * NDFv;
    float* Cx   = S + (size_t)MROWS * NCv;

    cudaFuncSetAttribute(gemm_mma_kernel, cudaFuncAttributeMaxDynamicSharedMemorySize, SMEM_TOTAL);

    bprep_kernel<<<dim3(KDIM / 32, NDFv / 32), 256>>>(w_emb);
    gemm_mma_kernel<<<128, NTHREADS, SMEM_TOTAL>>>(z_roi);
    reduce_kernel<<<(MROWS * NDFv / 2) / 256, 256>>>(b_emb, mask, zall);
    cluster_kernel<<<MROWS / 4, 128>>>(zall, cent, mask, S, Cx);
}

// round 12
// speedup vs baseline: 1.7645x; 1.1128x over previous
#include <cuda_runtime.h>
#include <cuda_fp16.h>
#include <cstdint>

#define KDIM   65536
#define MROWS  2048
#define NDFv   256
#define NCv    100
#define KC     64
#define NCTAS  148
#define TOTAL_UNITS 32768        // 32 mn-tiles * 1024 chunks
#define OFF_AH 0
#define OFF_AS 16384
#define OFF_BH 32768
#define OFF_BS 49152
#define STAGE  65536
#define SMEM_TOTAL (2 * STAGE)   // 128 KB

#define NTHREADS 320             // 256 consumers + 64 producers
#define KAPPA_INV 32.0f
#define ONE_MK    0.96875f       // 1 - 2^-5

// device-global scratch (no cudaMalloc allowed)
__device__ __align__(16) unsigned short g_Bh[(size_t)NDFv * KDIM]; // [n][k] fp16 rn(w)
__device__ __align__(16) unsigned short g_Bs[(size_t)NDFv * KDIM]; // [n][k] fp16 Bh+32*Bl
__device__ float g_partial[(size_t)2 * NCTAS * 16384];             // [cta*2+seg][128*128]

// ---------------- helpers (sm_80-class PTX only: valid on compute_103) ------
__device__ __forceinline__ uint32_t smem_u32(const void* p) {
    uint32_t a;
    asm("{ .reg .u64 t; cvta.to.shared.u64 t, %1; cvt.u32.u64 %0, t; }" : "=r"(a) : "l"(p));
    return a;
}
__device__ __forceinline__ uint32_t packh2(float lo, float hi) { // low half = rn16(lo)
    uint32_t r;
    asm("cvt.rn.f16x2.f32 %0, %1, %2;" : "=r"(r) : "f"(hi), "f"(lo));
    return r;
}
#define STS64V(a, r0, r1) \
    asm volatile("st.shared.v2.b32 [%0], {%1,%2};" :: "r"(a), "r"(r0), "r"(r1) : "memory")
#define CP_ASYNC16(dst, src) \
    asm volatile("cp.async.cg.shared.global [%0], [%1], 16;" :: "r"(dst), "l"(src) : "memory")
#define CP_COMMIT() asm volatile("cp.async.commit_group;" ::: "memory")
#define CP_WAIT0()  asm volatile("cp.async.wait_group 0;" ::: "memory")
#define MEMBAR_CTA() asm volatile("membar.cta;" ::: "memory")
#define BAR_SYNC(id)   asm volatile("bar.sync %0, %1;"   :: "r"(id), "r"(NTHREADS) : "memory")
#define BAR_ARRIVE(id) asm volatile("bar.arrive %0, %1;" :: "r"(id), "r"(NTHREADS) : "memory")
// barrier ids: 1+s = stage s FULL, 3+s = stage s EMPTY

__device__ __forceinline__ void ldsm4(uint32_t r[4], uint32_t a) {
    asm volatile("ldmatrix.sync.aligned.m8n8.x4.shared.b16 {%0,%1,%2,%3}, [%4];"
                 : "=r"(r[0]), "=r"(r[1]), "=r"(r[2]), "=r"(r[3]) : "r"(a));
}
__device__ __forceinline__ void mmaf16(float d[4], const uint32_t a[4],
                                       uint32_t b0, uint32_t b1) {
    asm volatile("mma.sync.aligned.m16n8k16.row.col.f32.f16.f16.f32 "
                 "{%0,%1,%2,%3},{%4,%5,%6,%7},{%8,%9},{%0,%1,%2,%3};"
                 : "+f"(d[0]), "+f"(d[1]), "+f"(d[2]), "+f"(d[3])
                 : "r"(a[0]), "r"(a[1]), "r"(a[2]), "r"(a[3]), "r"(b0), "r"(b1));
}

// ---------------- prepass: W [K,256] fp32 -> g_Bh/g_Bs [256][K] fp16 --------
__global__ __launch_bounds__(256) void bprep_kernel(const float* __restrict__ W) {
    __shared__ float tile[32][33];
    const int k0 = blockIdx.x * 32, n0 = blockIdx.y * 32;
    const int tx = threadIdx.x & 31, ty = threadIdx.x >> 5;
    #pragma unroll
    for (int i = 0; i < 4; i++)
        tile[ty * 4 + i][tx] = W[(size_t)(k0 + ty * 4 + i) * NDFv + n0 + tx];
    __syncthreads();
    #pragma unroll
    for (int i = 0; i < 4; i++) {
        const int n = ty * 4 + i;
        const float w = tile[tx][n];
        const __half bh = __float2half_rn(w);
        const float bhf = __half2float(bh);
        const float bl = w - bhf;
        const __half bs = __float2half_rn(fmaf(KAPPA_INV, bl, bhf));
        const size_t idx = (size_t)(n0 + n) * KDIM + k0 + tx;
        g_Bh[idx] = *(const unsigned short*)&bh;
        g_Bs[idx] = *(const unsigned short*)&bs;
    }
}

// ---------------- GEMM: fp16 2-pass kappa split, persistent balanced --------
__global__ __launch_bounds__(NTHREADS, 1) void gemm_mma_kernel(const float* __restrict__ A) {
    extern __shared__ char smem_dyn[];
    const uint32_t sbase = smem_u32(smem_dyn);
    const int tid = threadIdx.x;
    const int cta = blockIdx.x;
    const int u_begin = (cta * TOTAL_UNITS) / NCTAS;
    const int u_end   = ((cta + 1) * TOTAL_UNITS) / NCTAS;
    const int total   = u_end - u_begin;

    if (tid >= 256) {
        // ================= PRODUCER (warps 8-9, 64 threads) =================
        const int pt = tid - 256;             // 0..63
        const int prow = pt >> 4;             // A: row offset within group of 4
        const int pkf4 = pt & 15;             // A: float4 index within row-half
        const int prow8 = pt >> 3;            // B: row offset within group of 8
        const int pseg = pt & 7;              // B: 16B segment within row

        float4 bufA[8], bufB[8];

#define PLDG(buf, Ab, b) do {                                                    \
    _Pragma("unroll")                                                            \
    for (int j = 0; j < 8; j++) {                                                \
        const int row = (b) * 32 + j * 4 + prow;                                 \
        (buf)[j] = *(const float4*)((Ab) + (size_t)row * KDIM);                  \
    } } while (0)

#define PSTS(buf, st, b) do {                                                    \
    _Pragma("unroll")                                                            \
    for (int j = 0; j < 8; j++) {                                                \
        const int row = (b) * 32 + j * 4 + prow;                                 \
        const uint32_t off = (uint32_t)(row * 128) +                             \
                             (((uint32_t)(pkf4 * 8)) ^ ((uint32_t)((row & 7) << 4))); \
        const float4 f = (buf)[j];                                               \
        const uint32_t h0 = packh2(f.x, f.y);                                    \
        const uint32_t h1 = packh2(f.z, f.w);                                    \
        const float ahx = __half2float(*(const __half*)&h0);                     \
        const float ahy = __half2float(((const __half*)&h0)[1]);                 \
        const float ahz = __half2float(*(const __half*)&h1);                     \
        const float ahw = __half2float(((const __half*)&h1)[1]);                 \
        const uint32_t s0 = packh2(fmaf(-ONE_MK, ahx, f.x), fmaf(-ONE_MK, ahy, f.y)); \
        const uint32_t s1 = packh2(fmaf(-ONE_MK, ahz, f.z), fmaf(-ONE_MK, ahw, f.w)); \
        STS64V((st) + OFF_AH + off, h0, h1);                                     \
        STS64V((st) + OFF_AS + off, s0, s1);                                     \
    } } while (0)

        for (int it = 0; it < total; it++) {
            const int s = it & 1;
            const uint32_t st = sbase + (uint32_t)(s * STAGE);
            if (it >= 2) BAR_SYNC(3 + s);        // wait stage empty

            const int u  = u_begin + it;
            const int mt = u >> 11;              // tile>>1
            const int nt = (u >> 10) & 1;
            const int ch = u & 1023;

            // B -> cp.async (fills while we convert A)
            {
                const unsigned short* bh = g_Bh + (size_t)(nt * 128) * KDIM
                                           + (size_t)ch * KC + pseg * 8;
                const unsigned short* bs = g_Bs + (size_t)(nt * 128) * KDIM
                                           + (size_t)ch * KC + pseg * 8;
                #pragma unroll
                for (int j = 0; j < 16; j++) {
                    const int row = j * 8 + prow8;
                    const uint32_t off = (uint32_t)(row * 128) +
                        (((uint32_t)(pseg * 16)) ^ ((uint32_t)(prow8 << 4)));
                    CP_ASYNC16(st + OFF_BH + off, bh + (size_t)row * KDIM);
                    CP_ASYNC16(st + OFF_BS + off, bs + (size_t)row * KDIM);
                }
                CP_COMMIT();
            }
            // A: 4 batches, reg double-buffered
            const float* Ab = A + (size_t)(mt * 128) * KDIM + (size_t)ch * KC
                              + pkf4 * 4 + (pt & 16 ? 0 : 0);
            // NOTE: 2 threads per row via prow covering rows, pkf4 covers 16 float4 = full 64k row
            PLDG(bufA, Ab, 0);
            PLDG(bufB, Ab, 1);
            PSTS(bufA, st, 0);
            PLDG(bufA, Ab, 2);
            PSTS(bufB, st, 1);
            PLDG(bufB, Ab, 3);
            PSTS(bufA, st, 2);
            PSTS(bufB, st, 3);
            CP_WAIT0();
            MEMBAR_CTA();
            BAR_ARRIVE(1 + s);                   // publish stage full
        }
        return;
    }

    // ================= CONSUMERS (warps 0-7, 256 threads) ===================
    const int wid = tid >> 5, lane = tid & 31;
    const int wm = wid & 1, wn = wid >> 1;       // warp tile: m64 x n32

    const int a_r = (lane & 7) + ((lane >> 3) & 1) * 8;
    const uint32_t a_c16 = (uint32_t)(((lane >> 4) & 1) * 16);
    const uint32_t xf = (uint32_t)((a_r & 7) << 4);
    uint32_t colx[4];
    #pragma unroll
    for (int ks = 0; ks < 4; ks++) colx[ks] = (((uint32_t)ks << 5) | a_c16) ^ xf;

    float acc1[4][4][4] = {};   // P1 = Ah*Bh
    float acc2[4][4][4] = {};   // P2 = As*Bs
    int slot = cta * 2;

#define KSTEP(ks) do {                                                           \
    uint32_t ah[4][4], bh[2][4];                                                 \
    _Pragma("unroll")                                                            \
    for (int mf = 0; mf < 4; mf++)                                               \
        ldsm4(ah[mf], st + OFF_AH + (uint32_t)((wm * 64 + mf * 16 + a_r) * 128) + colx[ks]); \
    _Pragma("unroll")                                                            \
    for (int g = 0; g < 2; g++)                                                  \
        ldsm4(bh[g], st + OFF_BH + (uint32_t)((wn * 32 + g * 16 + a_r) * 128) + colx[ks]);   \
    _Pragma("unroll")                                                            \
    for (int mf = 0; mf < 4; mf++)                                               \
        _Pragma("unroll")                                                        \
        for (int g = 0; g < 2; g++) {                                            \
            mmaf16(acc1[mf][g * 2 + 0], ah[mf], bh[g][0], bh[g][2]);             \
            mmaf16(acc1[mf][g * 2 + 1], ah[mf], bh[g][1], bh[g][3]);             \
        }                                                                        \
    uint32_t as[4][4], bs[2][4];                                                 \
    _Pragma("unroll")                                                            \
    for (int mf = 0; mf < 4; mf++)                                               \
        ldsm4(as[mf], st + OFF_AS + (uint32_t)((wm * 64 + mf * 16 + a_r) * 128) + colx[ks]); \
    _Pragma("unroll")                                                            \
    for (int g = 0; g < 2; g++)                                                  \
        ldsm4(bs[g], st + OFF_BS + (uint32_t)((wn * 32 + g * 16 + a_r) * 128) + colx[ks]);   \
    _Pragma("unroll")                                                            \
    for (int mf = 0; mf < 4; mf++)                                               \
        _Pragma("unroll")                                                        \
        for (int g = 0; g < 2; g++) {                                            \
            mmaf16(acc2[mf][g * 2 + 0], as[mf], bs[g][0], bs[g][2]);             \
            mmaf16(acc2[mf][g * 2 + 1], as[mf], bs[g][1], bs[g][3]);             \
        } } while (0)

    for (int it = 0; it < total; it++) {
        const int s = it & 1;
        const uint32_t st = sbase + (uint32_t)(s * STAGE);
        BAR_SYNC(1 + s);                 // wait stage full
        KSTEP(0);
        KSTEP(1);
        KSTEP(2);
        KSTEP(3);
        if (it + 2 < total) BAR_ARRIVE(3 + s);   // signal stage empty

        const int u = u_begin + it;
        if (it == total - 1 || ((u + 1) & 1023) == 0) {
            // tile segment done: flush to slot, reset accumulators
            float* pb = g_partial + (size_t)slot * 16384;
            #pragma unroll
            for (int mf = 0; mf < 4; mf++)
                #pragma unroll
                for (int nf = 0; nf < 4; nf++) {
                    const int rl = wm * 64 + mf * 16 + (lane >> 2);
                    const int cl = wn * 32 + nf * 8 + (lane & 3) * 2;
                    const float v0 = fmaf(ONE_MK, acc1[mf][nf][0], acc2[mf][nf][0]);
                    const float v1 = fmaf(ONE_MK, acc1[mf][nf][1], acc2[mf][nf][1]);
                    const float v2 = fmaf(ONE_MK, acc1[mf][nf][2], acc2[mf][nf][2]);
                    const float v3 = fmaf(ONE_MK, acc1[mf][nf][3], acc2[mf][nf][3]);
                    *(float2*)(pb + rl * 128 + cl) = make_float2(v0, v1);
                    *(float2*)(pb + (rl + 8) * 128 + cl) = make_float2(v2, v3);
                    acc1[mf][nf][0] = acc1[mf][nf][1] = acc1[mf][nf][2] = acc1[mf][nf][3] = 0.f;
                    acc2[mf][nf][0] = acc2[mf][nf][1] = acc2[mf][nf][2] = acc2[mf][nf][3] = 0.f;
                }
            slot++;
        }
    }
}

// ---------------- reduce: zall = (sum of contributing slots + bias) * mask --
__global__ __launch_bounds__(256) void reduce_kernel(const float* __restrict__ bias,
                                                     const int* __restrict__ mask,
                                                     float* __restrict__ zall) {
    const int i = blockIdx.x * 256 + threadIdx.x;   // float2 units
    const int row = i >> 7;
    const int col = (i & 127) * 2;
    const int t = ((row >> 7) << 1) | (col >> 7);   // mn-tile index 0..31
    const int rl = row & 127, cl = col & 127;

    float2 s = make_float2(0.f, 0.f);
    int c0 = (t << 10) * NCTAS / TOTAL_UNITS - 1;
    if (c0 < 0) c0 = 0;
    #pragma unroll 1
    for (int c = c0; c < c0 + 8; c++) {
        if (c >= NCTAS) break;
        const int u0 = (c * TOTAL_UNITS) / NCTAS;
        const int u1 = ((c + 1) * TOTAL_UNITS) / NCTAS;
        if (u0 < ((t + 1) << 10) && u1 > (t << 10)) {
            const int seg = ((u0 >> 10) == t) ? 0 : 1;
            const float2 v = *(const float2*)(g_partial +
                (size_t)(c * 2 + seg) * 16384 + rl * 128 + cl);
            s.x += v.x; s.y += v.y;
        }
    }
    const float m = mask[row] ? 1.0f : 0.0f;
    s.x = (s.x + bias[col]) * m;
    s.y = (s.y + bias[col + 1]) * m;
    *(float2*)&zall[(size_t)row * NDFv + col] = s;
}

// ---------------- student-t + normalize + argmax (4 rows / block) -----------
__global__ __launch_bounds__(128) void cluster_kernel(const float* __restrict__ Z,
                                                      const float* __restrict__ cent,
                                                      const int* __restrict__ mask,
                                                      float* __restrict__ S,
                                                      float* __restrict__ Cidx) {
    const int tid = threadIdx.x;
    const int row0 = blockIdx.x * 4;
    __shared__ __align__(16) float zs[4][256];
    __shared__ float stmp[4][128];
    __shared__ float red_s[4];
    __shared__ int   red_i[4];

    #pragma unroll
    for (int i = 0; i < 8; i++) {
        const int idx = i * 128 + tid;
        zs[idx >> 8][idx & 255] = Z[(size_t)row0 * 256 + idx];
    }
    __syncthreads();

    float v[4] = {0.f, 0.f, 0.f, 0.f};
    if (tid < NCv) {
        const float4* c4 = (const float4*)(cent + (size_t)tid * NDFv);
        float d[4] = {0.f, 0.f, 0.f, 0.f};
        #pragma unroll 4
        for (int j = 0; j < NDFv / 4; j++) {
            const float4 cv = c4[j];
            #pragma unroll
            for (int r = 0; r < 4; r++) {
                const float4 zv = ((const float4*)zs[r])[j];
                const float dx = zv.x - cv.x, dy = zv.y - cv.y;
                const float dz = zv.z - cv.z, dw = zv.w - cv.w;
                d[r] += dx * dx + dy * dy + dz * dz + dw * dw;
            }
        }
        #pragma unroll
        for (int r = 0; r < 4; r++)
            v[r] = 1.0f / (1.0f + sqrtf(fmaxf(d[r], 0.0f)));
    }
    #pragma unroll
    for (int r = 0; r < 4; r++) stmp[r][tid] = v[r];
    __syncthreads();

    {   // warp r reduces row r
        const int r = tid >> 5, l = tid & 31;
        float sum = 0.0f, best = -1.0f;
        int bidx = 0;
        for (int k = l; k < NCv; k += 32) {
            const float x = stmp[r][k];
            sum += x;
            if (x > best) { best = x; bidx = k; }
        }
        #pragma unroll
        for (int off = 16; off > 0; off >>= 1) {
            sum += __shfl_down_sync(0xffffffffu, sum, off);
            const float ob = __shfl_down_sync(0xffffffffu, best, off);
            const int   oi = __shfl_down_sync(0xffffffffu, bidx, off);
            if (ob > best || (ob == best && oi < bidx)) { best = ob; bidx = oi; }
        }
        if (l == 0) { red_s[r] = sum; red_i[r] = bidx; }
    }
    __syncthreads();

    #pragma unroll
    for (int r = 0; r < 4; r++) {
        const int row = row0 + r;
        const bool m = mask[row] != 0;
        const float inv = m ? (1.0f / red_s[r]) : 0.0f;
        if (tid < NCv) S[(size_t)row * NCv + tid] = v[r] * inv;
        if (tid == 0)  Cidx[row] = m ? (float)red_i[r] : 0.0f;
    }
}

// ---------------------------------------------------------------------------
extern "C" void kernel_launch(void* const* d_in, const int* in_sizes, int n_in,
                              void* d_out, int out_size) {
    (void)in_sizes; (void)n_in; (void)out_size;
    const float* z_roi = (const float*)d_in[0];
    const int*   mask  = (const int*)d_in[1];
    const float* w_emb = (const float*)d_in[2];
    const float* b_emb = (const float*)d_in[3];
    const float* cent  = (const float*)d_in[4];

    float* out  = (float*)d_out;
    float* zall = out;
    float* S    = out + (size_t)MROWS * NDFv;
    float* Cx   = S + (size_t)MROWS * NCv;

    cudaFuncSetAttribute(gemm_mma_kernel, cudaFuncAttributeMaxDynamicSharedMemorySize, SMEM_TOTAL);

    bprep_kernel<<<dim3(KDIM / 32, NDFv / 32), 256>>>(w_emb);
    gemm_mma_kernel<<<NCTAS, NTHREADS, SMEM_TOTAL>>>(z_roi);
    reduce_kernel<<<(MROWS * NDFv / 2) / 256, 256>>>(b_emb, mask, zall);
    cluster_kernel<<<MROWS / 4, 128>>>(zall, cent, mask, S, Cx);
}

// round 13
// speedup vs baseline: 1.7771x; 1.0072x over previous
#include <cuda_runtime.h>
#include <cuda_fp16.h>
#include <cstdint>

#define KDIM   65536
#define MROWS  2048
#define NDFv   256
#define NCv    100
#define KC     64
#define NCTAS  148
#define TOTAL_UNITS 32768        // 32 mn-tiles * 1024 chunks
#define OFF_AH 0
#define OFF_AS 16384
#define OFF_BH 32768
#define OFF_BS 49152
#define STAGE  65536
#define SMEM_TOTAL (2 * STAGE)   // 128 KB

#define NTHREADS 320             // 256 consumers + 64 producers
#define KAPPA_INV 32.0f
#define ONE_MK    0.96875f       // 1 - 2^-5

// device-global scratch (no cudaMalloc allowed)
__device__ __align__(16) unsigned short g_Bh[(size_t)NDFv * KDIM]; // [n][k] fp16 rn(w)
__device__ __align__(16) unsigned short g_Bs[(size_t)NDFv * KDIM]; // [n][k] fp16 Bh+32*Bl
__device__ float g_partial[(size_t)2 * NCTAS * 16384];             // [cta*2+seg][128*128]

// ---------------- helpers (sm_80-class PTX only: valid on compute_103) ------
__device__ __forceinline__ uint32_t smem_u32(const void* p) {
    uint32_t a;
    asm("{ .reg .u64 t; cvta.to.shared.u64 t, %1; cvt.u32.u64 %0, t; }" : "=r"(a) : "l"(p));
    return a;
}
__device__ __forceinline__ uint32_t packh2(float lo, float hi) { // low half = rn16(lo)
    uint32_t r;
    asm("cvt.rn.f16x2.f32 %0, %1, %2;" : "=r"(r) : "f"(hi), "f"(lo));
    return r;
}
#define STS64V(a, r0, r1) \
    asm volatile("st.shared.v2.b32 [%0], {%1,%2};" :: "r"(a), "r"(r0), "r"(r1) : "memory")
#define CP_ASYNC16(dst, src) \
    asm volatile("cp.async.cg.shared.global [%0], [%1], 16;" :: "r"(dst), "l"(src) : "memory")
#define CP_COMMIT() asm volatile("cp.async.commit_group;" ::: "memory")
#define CP_WAIT0()  asm volatile("cp.async.wait_group 0;" ::: "memory")
#define MEMBAR_CTA() asm volatile("membar.cta;" ::: "memory")
#define BAR_SYNC(id)   asm volatile("bar.sync %0, %1;"   :: "r"(id), "r"(NTHREADS) : "memory")
#define BAR_ARRIVE(id) asm volatile("bar.arrive %0, %1;" :: "r"(id), "r"(NTHREADS) : "memory")
// barrier ids: 1+s = stage s FULL, 3+s = stage s EMPTY

__device__ __forceinline__ void ldsm4(uint32_t r[4], uint32_t a) {
    asm volatile("ldmatrix.sync.aligned.m8n8.x4.shared.b16 {%0,%1,%2,%3}, [%4];"
                 : "=r"(r[0]), "=r"(r[1]), "=r"(r[2]), "=r"(r[3]) : "r"(a));
}
__device__ __forceinline__ void mmaf16(float d[4], const uint32_t a[4],
                                       uint32_t b0, uint32_t b1) {
    asm volatile("mma.sync.aligned.m16n8k16.row.col.f32.f16.f16.f32 "
                 "{%0,%1,%2,%3},{%4,%5,%6,%7},{%8,%9},{%0,%1,%2,%3};"
                 : "+f"(d[0]), "+f"(d[1]), "+f"(d[2]), "+f"(d[3])
                 : "r"(a[0]), "r"(a[1]), "r"(a[2]), "r"(a[3]), "r"(b0), "r"(b1));
}

// ---------------- prepass: W [K,256] fp32 -> g_Bh/g_Bs [256][K] fp16 --------
__global__ __launch_bounds__(256) void bprep_kernel(const float* __restrict__ W) {
    __shared__ float tile[32][33];
    const int k0 = blockIdx.x * 32, n0 = blockIdx.y * 32;
    const int tx = threadIdx.x & 31, ty = threadIdx.x >> 5;
    #pragma unroll
    for (int i = 0; i < 4; i++)
        tile[ty * 4 + i][tx] = W[(size_t)(k0 + ty * 4 + i) * NDFv + n0 + tx];
    __syncthreads();
    #pragma unroll
    for (int i = 0; i < 4; i++) {
        const int n = ty * 4 + i;
        const float w = tile[tx][n];
        const __half bh = __float2half_rn(w);
        const float bhf = __half2float(bh);
        const float bl = w - bhf;
        const __half bs = __float2half_rn(fmaf(KAPPA_INV, bl, bhf));
        const size_t idx = (size_t)(n0 + n) * KDIM + k0 + tx;
        g_Bh[idx] = *(const unsigned short*)&bh;
        g_Bs[idx] = *(const unsigned short*)&bs;
    }
}

// ---------------- GEMM: fp16 2-pass kappa split, persistent balanced --------
__global__ __launch_bounds__(NTHREADS, 1) void gemm_mma_kernel(const float* __restrict__ A) {
    extern __shared__ char smem_dyn[];
    const uint32_t sbase = smem_u32(smem_dyn);
    const int tid = threadIdx.x;
    const int cta = blockIdx.x;
    const int u_begin = (cta * TOTAL_UNITS) / NCTAS;
    const int u_end   = ((cta + 1) * TOTAL_UNITS) / NCTAS;
    const int total   = u_end - u_begin;

    if (tid >= 256) {
        // ================= PRODUCER (warps 8-9, 64 threads) =================
        const int pt = tid - 256;             // 0..63
        const int prow = pt >> 4;             // A: row offset within group of 4
        const int pkf4 = pt & 15;             // A: float4 index within row-half
        const int prow8 = pt >> 3;            // B: row offset within group of 8
        const int pseg = pt & 7;              // B: 16B segment within row

        float4 bufA[8], bufB[8];

#define PLDG(buf, Ab, b) do {                                                    \
    _Pragma("unroll")                                                            \
    for (int j = 0; j < 8; j++) {                                                \
        const int row = (b) * 32 + j * 4 + prow;                                 \
        (buf)[j] = *(const float4*)((Ab) + (size_t)row * KDIM);                  \
    } } while (0)

#define PSTS(buf, st, b) do {                                                    \
    _Pragma("unroll")                                                            \
    for (int j = 0; j < 8; j++) {                                                \
        const int row = (b) * 32 + j * 4 + prow;                                 \
        const uint32_t off = (uint32_t)(row * 128) +                             \
                             (((uint32_t)(pkf4 * 8)) ^ ((uint32_t)((row & 7) << 4))); \
        const float4 f = (buf)[j];                                               \
        const uint32_t h0 = packh2(f.x, f.y);                                    \
        const uint32_t h1 = packh2(f.z, f.w);                                    \
        const float ahx = __half2float(*(const __half*)&h0);                     \
        const float ahy = __half2float(((const __half*)&h0)[1]);                 \
        const float ahz = __half2float(*(const __half*)&h1);                     \
        const float ahw = __half2float(((const __half*)&h1)[1]);                 \
        const uint32_t s0 = packh2(fmaf(-ONE_MK, ahx, f.x), fmaf(-ONE_MK, ahy, f.y)); \
        const uint32_t s1 = packh2(fmaf(-ONE_MK, ahz, f.z), fmaf(-ONE_MK, ahw, f.w)); \
        STS64V((st) + OFF_AH + off, h0, h1);                                     \
        STS64V((st) + OFF_AS + off, s0, s1);                                     \
    } } while (0)

        for (int it = 0; it < total; it++) {
            const int s = it & 1;
            const uint32_t st = sbase + (uint32_t)(s * STAGE);
            if (it >= 2) BAR_SYNC(3 + s);        // wait stage empty

            const int u  = u_begin + it;
            const int mt = u >> 11;              // tile>>1
            const int nt = (u >> 10) & 1;
            const int ch = u & 1023;

            // B -> cp.async (fills while we convert A)
            {
                const unsigned short* bh = g_Bh + (size_t)(nt * 128) * KDIM
                                           + (size_t)ch * KC + pseg * 8;
                const unsigned short* bs = g_Bs + (size_t)(nt * 128) * KDIM
                                           + (size_t)ch * KC + pseg * 8;
                #pragma unroll
                for (int j = 0; j < 16; j++) {
                    const int row = j * 8 + prow8;
                    const uint32_t off = (uint32_t)(row * 128) +
                        (((uint32_t)(pseg * 16)) ^ ((uint32_t)(prow8 << 4)));
                    CP_ASYNC16(st + OFF_BH + off, bh + (size_t)row * KDIM);
                    CP_ASYNC16(st + OFF_BS + off, bs + (size_t)row * KDIM);
                }
                CP_COMMIT();
            }
            // A: 4 batches, reg double-buffered
            const float* Ab = A + (size_t)(mt * 128) * KDIM + (size_t)ch * KC
                              + pkf4 * 4;
            PLDG(bufA, Ab, 0);
            PLDG(bufB, Ab, 1);
            PSTS(bufA, st, 0);
            PLDG(bufA, Ab, 2);
            PSTS(bufB, st, 1);
            PLDG(bufB, Ab, 3);
            PSTS(bufA, st, 2);
            PSTS(bufB, st, 3);
            CP_WAIT0();
            MEMBAR_CTA();
            BAR_ARRIVE(1 + s);                   // publish stage full
        }
        return;
    }

    // ================= CONSUMERS (warps 0-7, 256 threads) ===================
    const int wid = tid >> 5, lane = tid & 31;
    const int wm = wid & 1, wn = wid >> 1;       // warp tile: m64 x n32

    const int a_r = (lane & 7) + ((lane >> 3) & 1) * 8;
    const uint32_t a_c16 = (uint32_t)(((lane >> 4) & 1) * 16);
    const uint32_t xf = (uint32_t)((a_r & 7) << 4);
    uint32_t colx[4];
    #pragma unroll
    for (int ks = 0; ks < 4; ks++) colx[ks] = (((uint32_t)ks << 5) | a_c16) ^ xf;

    float acc1[4][4][4] = {};   // P1 = Ah*Bh
    float acc2[4][4][4] = {};   // P2 = As*Bs
    int slot = cta * 2;

#define KSTEP(ks) do {                                                           \
    uint32_t ah[4][4], bh[2][4];                                                 \
    _Pragma("unroll")                                                            \
    for (int mf = 0; mf < 4; mf++)                                               \
        ldsm4(ah[mf], st + OFF_AH + (uint32_t)((wm * 64 + mf * 16 + a_r) * 128) + colx[ks]); \
    _Pragma("unroll")                                                            \
    for (int g = 0; g < 2; g++)                                                  \
        ldsm4(bh[g], st + OFF_BH + (uint32_t)((wn * 32 + g * 16 + a_r) * 128) + colx[ks]);   \
    _Pragma("unroll")                                                            \
    for (int mf = 0; mf < 4; mf++)                                               \
        _Pragma("unroll")                                                        \
        for (int g = 0; g < 2; g++) {                                            \
            mmaf16(acc1[mf][g * 2 + 0], ah[mf], bh[g][0], bh[g][2]);             \
            mmaf16(acc1[mf][g * 2 + 1], ah[mf], bh[g][1], bh[g][3]);             \
        }                                                                        \
    uint32_t as[4][4], bs[2][4];                                                 \
    _Pragma("unroll")                                                            \
    for (int mf = 0; mf < 4; mf++)                                               \
        ldsm4(as[mf], st + OFF_AS + (uint32_t)((wm * 64 + mf * 16 + a_r) * 128) + colx[ks]); \
    _Pragma("unroll")                                                            \
    for (int g = 0; g < 2; g++)                                                  \
        ldsm4(bs[g], st + OFF_BS + (uint32_t)((wn * 32 + g * 16 + a_r) * 128) + colx[ks]);   \
    _Pragma("unroll")                                                            \
    for (int mf = 0; mf < 4; mf++)                                               \
        _Pragma("unroll")                                                        \
        for (int g = 0; g < 2; g++) {                                            \
            mmaf16(acc2[mf][g * 2 + 0], as[mf], bs[g][0], bs[g][2]);             \
            mmaf16(acc2[mf][g * 2 + 1], as[mf], bs[g][1], bs[g][3]);             \
        } } while (0)

    for (int it = 0; it < total; it++) {
        const int s = it & 1;
        const uint32_t st = sbase + (uint32_t)(s * STAGE);
        BAR_SYNC(1 + s);                 // wait stage full
        KSTEP(0);
        KSTEP(1);
        KSTEP(2);
        KSTEP(3);
        if (it + 2 < total) BAR_ARRIVE(3 + s);   // signal stage empty

        const int u = u_begin + it;
        if (it == total - 1 || ((u + 1) & 1023) == 0) {
            // tile segment done: flush to slot, reset accumulators
            float* pb = g_partial + (size_t)slot * 16384;
            #pragma unroll
            for (int mf = 0; mf < 4; mf++)
                #pragma unroll
                for (int nf = 0; nf < 4; nf++) {
                    const int rl = wm * 64 + mf * 16 + (lane >> 2);
                    const int cl = wn * 32 + nf * 8 + (lane & 3) * 2;
                    const float v0 = fmaf(ONE_MK, acc1[mf][nf][0], acc2[mf][nf][0]);
                    const float v1 = fmaf(ONE_MK, acc1[mf][nf][1], acc2[mf][nf][1]);
                    const float v2 = fmaf(ONE_MK, acc1[mf][nf][2], acc2[mf][nf][2]);
                    const float v3 = fmaf(ONE_MK, acc1[mf][nf][3], acc2[mf][nf][3]);
                    *(float2*)(pb + rl * 128 + cl) = make_float2(v0, v1);
                    *(float2*)(pb + (rl + 8) * 128 + cl) = make_float2(v2, v3);
                    acc1[mf][nf][0] = acc1[mf][nf][1] = acc1[mf][nf][2] = acc1[mf][nf][3] = 0.f;
                    acc2[mf][nf][0] = acc2[mf][nf][1] = acc2[mf][nf][2] = acc2[mf][nf][3] = 0.f;
                }
            slot++;
        }
    }
}

// ---------------- reduce: zall = (sum of contributing slots + bias) * mask --
__global__ __launch_bounds__(256) void reduce_kernel(const float* __restrict__ bias,
                                                     const int* __restrict__ mask,
                                                     float* __restrict__ zall) {
    const int i = blockIdx.x * 256 + threadIdx.x;   // float2 units
    const int row = i >> 7;
    const int col = (i & 127) * 2;
    const int t = ((row >> 7) << 1) | (col >> 7);   // mn-tile index 0..31
    const int rl = row & 127, cl = col & 127;

    float2 s = make_float2(0.f, 0.f);
    int c0 = (t << 10) * NCTAS / TOTAL_UNITS - 1;
    if (c0 < 0) c0 = 0;
    #pragma unroll 1
    for (int c = c0; c < c0 + 8; c++) {
        if (c >= NCTAS) break;
        const int u0 = (c * TOTAL_UNITS) / NCTAS;
        const int u1 = ((c + 1) * TOTAL_UNITS) / NCTAS;
        if (u0 < ((t + 1) << 10) && u1 > (t << 10)) {
            const int seg = ((u0 >> 10) == t) ? 0 : 1;
            const float2 v = *(const float2*)(g_partial +
                (size_t)(c * 2 + seg) * 16384 + rl * 128 + cl);
            s.x += v.x; s.y += v.y;
        }
    }
    const float m = mask[row] ? 1.0f : 0.0f;
    s.x = (s.x + bias[col]) * m;
    s.y = (s.y + bias[col + 1]) * m;
    *(float2*)&zall[(size_t)row * NDFv + col] = s;
}

// ---------------- student-t + normalize + argmax (8 rows / block, ILP x8) ---
__global__ __launch_bounds__(128) void cluster_kernel(const float* __restrict__ Z,
                                                      const float* __restrict__ cent,
                                                      const int* __restrict__ mask,
                                                      float* __restrict__ S,
                                                      float* __restrict__ Cidx) {
    const int tid = threadIdx.x;
    const int row0 = blockIdx.x * 8;
    __shared__ __align__(16) float zs[8][256];
    __shared__ float stmp[8][128];
    __shared__ float red_s[8];
    __shared__ int   red_i[8];

    #pragma unroll
    for (int i = 0; i < 16; i++) {
        const int idx = i * 128 + tid;
        zs[idx >> 8][idx & 255] = Z[(size_t)row0 * 256 + idx];
    }
    __syncthreads();

    float v[8] = {0.f, 0.f, 0.f, 0.f, 0.f, 0.f, 0.f, 0.f};
    if (tid < NCv) {
        const float4* c4 = (const float4*)(cent + (size_t)tid * NDFv);
        float d[8] = {0.f, 0.f, 0.f, 0.f, 0.f, 0.f, 0.f, 0.f};
        #pragma unroll 2
        for (int j = 0; j < NDFv / 4; j++) {
            const float4 cv = c4[j];
            #pragma unroll
            for (int r = 0; r < 8; r++) {
                const float4 zv = ((const float4*)zs[r])[j];
                const float dx = zv.x - cv.x, dy = zv.y - cv.y;
                const float dz = zv.z - cv.z, dw = zv.w - cv.w;
                d[r] += dx * dx + dy * dy + dz * dz + dw * dw;
            }
        }
        #pragma unroll
        for (int r = 0; r < 8; r++)
            v[r] = 1.0f / (1.0f + sqrtf(fmaxf(d[r], 0.0f)));
    }
    #pragma unroll
    for (int r = 0; r < 8; r++) stmp[r][tid] = v[r];
    __syncthreads();

    #pragma unroll
    for (int pass = 0; pass < 2; pass++) {   // warp w reduces rows w and w+4
        const int r = (tid >> 5) + pass * 4;
        const int l = tid & 31;
        float sum = 0.0f, best = -1.0f;
        int bidx = 0;
        for (int k = l; k < NCv; k += 32) {
            const float x = stmp[r][k];
            sum += x;
            if (x > best) { best = x; bidx = k; }
        }
        #pragma unroll
        for (int off = 16; off > 0; off >>= 1) {
            sum += __shfl_down_sync(0xffffffffu, sum, off);
            const float ob = __shfl_down_sync(0xffffffffu, best, off);
            const int   oi = __shfl_down_sync(0xffffffffu, bidx, off);
            if (ob > best || (ob == best && oi < bidx)) { best = ob; bidx = oi; }
        }
        if (l == 0) { red_s[r] = sum; red_i[r] = bidx; }
    }
    __syncthreads();

    #pragma unroll
    for (int r = 0; r < 8; r++) {
        const int row = row0 + r;
        const bool m = mask[row] != 0;
        const float inv = m ? (1.0f / red_s[r]) : 0.0f;
        if (tid < NCv) S[(size_t)row * NCv + tid] = v[r] * inv;
        if (tid == 0)  Cidx[row] = m ? (float)red_i[r] : 0.0f;
    }
}

// ---------------------------------------------------------------------------
extern "C" void kernel_launch(void* const* d_in, const int* in_sizes, int n_in,
                              void* d_out, int out_size) {
    (void)in_sizes; (void)n_in; (void)out_size;
    const float* z_roi = (const float*)d_in[0];
    const int*   mask  = (const int*)d_in[1];
    const float* w_emb = (const float*)d_in[2];
    const float* b_emb = (const float*)d_in[3];
    const float* cent  = (const float*)d_in[4];

    float* out  = (float*)d_out;
    float* zall = out;
    float* S    = out + (size_t)MROWS * NDFv;
    float* Cx   = S + (size_t)MROWS * NCv;

    cudaFuncSetAttribute(gemm_mma_kernel, cudaFuncAttributeMaxDynamicSharedMemorySize, SMEM_TOTAL);

    bprep_kernel<<<dim3(KDIM / 32, NDFv / 32), 256>>>(w_emb);
    gemm_mma_kernel<<<NCTAS, NTHREADS, SMEM_TOTAL>>>(z_roi);
    reduce_kernel<<<(MROWS * NDFv / 2) / 256, 256>>>(b_emb, mask, zall);
    cluster_kernel<<<MROWS / 8, 128>>>(zall, cent, mask, S, Cx);
}